// round 1
// baseline (speedup 1.0000x reference)
#include <cuda_runtime.h>
#include <cuda_bf16.h>
#include <cstdint>

#define BB 4
#define NN 8192
#define NPOINT 2048
#define CC 64
#define NS 32
#define NSP 33      // NSAMPLE + 1 (fps_idx prepended)
#define TOTCH 70    // 3 + 3 + 64

// Scratch (device globals — no allocations allowed)
__device__ int   g_idx[BB * NPOINT * NSP];
__device__ float g_sx[BB * NN];
__device__ float g_sy[BB * NN];
__device__ float g_sz[BB * NN];

// ---------------------------------------------------------------------------
// Kernel A: transpose xyz (B,N,3) AoS -> SoA for coalesced ball-query loads
// ---------------------------------------------------------------------------
__global__ void soa_kernel(const float* __restrict__ xyz) {
    int t = blockIdx.x * blockDim.x + threadIdx.x;
    if (t >= BB * NN) return;
    g_sx[t] = xyz[t * 3 + 0];
    g_sy[t] = xyz[t * 3 + 1];
    g_sz[t] = xyz[t * 3 + 2];
}

// ---------------------------------------------------------------------------
// Kernel B: ball query — one warp per centroid, ballot prefix-scan collection
// Semantics (faithful to pointnet2): scan i=0..N-1 in order, collect first
// NSAMPLE indices with d2 < r^2; pad remaining slots with first hit (0 if
// empty ball); slot 0 = fps_idx.
// ---------------------------------------------------------------------------
__global__ void ball_query_kernel(const float* __restrict__ new_xyz,
                                  const int* __restrict__ fps_idx) {
    const int lane = threadIdx.x & 31;
    const int w = (blockIdx.x * blockDim.x + threadIdx.x) >> 5;
    if (w >= BB * NPOINT) return;
    const int b = w / NPOINT;

    const float cx = __ldg(&new_xyz[w * 3 + 0]);
    const float cy = __ldg(&new_xyz[w * 3 + 1]);
    const float cz = __ldg(&new_xyz[w * 3 + 2]);
    const float r2 = __fmul_rn(0.1f, 0.1f);

    const float* __restrict__ sx = g_sx + b * NN;
    const float* __restrict__ sy = g_sy + b * NN;
    const float* __restrict__ sz = g_sz + b * NN;
    int* __restrict__ out = g_idx + w * NSP;

    int count = 0;
    int first = -1;
    const unsigned below = (1u << lane) - 1u;

    for (int base = 0; base < NN; base += 32) {
        const int i = base + lane;
        // Non-FMA, left-associated: matches XLA's (dx^2 + dy^2) + dz^2 exactly
        const float dx = __fsub_rn(cx, sx[i]);
        const float dy = __fsub_rn(cy, sy[i]);
        const float dz = __fsub_rn(cz, sz[i]);
        const float d2 = __fadd_rn(
            __fadd_rn(__fmul_rn(dx, dx), __fmul_rn(dy, dy)),
            __fmul_rn(dz, dz));
        const bool valid = d2 < r2;
        const unsigned m = __ballot_sync(0xffffffffu, valid);
        if (first < 0 && m != 0u) first = base + __ffs(m) - 1;
        if (valid) {
            const int pos = count + __popc(m & below);
            if (pos < NS) out[1 + pos] = i;
        }
        count += __popc(m);
        if (count >= NS) break;
    }

    // Padding: slots [count, NS) get first-hit index (0 if empty)
    const int pad = (first >= 0) ? first : 0;
    if (lane < NS && lane >= count) out[1 + lane] = pad;
    if (lane == 0) out[0] = fps_idx[w];
}

// ---------------------------------------------------------------------------
// Kernel C: gather + center + concat -> out (B, 70, NPOINT, 33)
//   ch 0-2 : xyz[idx] - new_xyz   (channel ch)
//   ch 3-5 : same centered again  (channel ch-3)
//   ch 6-69: features[ch-6][idx]
// ---------------------------------------------------------------------------
__global__ void gather_kernel(const float* __restrict__ new_xyz,
                              const float* __restrict__ features,
                              float* __restrict__ out) {
    const int total = BB * TOTCH * NPOINT * NSP;
    int t = blockIdx.x * blockDim.x + threadIdx.x;
    if (t >= total) return;

    const int s  = t % NSP;
    int rem      = t / NSP;
    const int j  = rem % NPOINT;
    rem          = rem / NPOINT;
    const int ch = rem % TOTCH;
    const int b  = rem / TOTCH;

    const int i = g_idx[(b * NPOINT + j) * NSP + s];

    float val;
    if (ch < 6) {
        const int k = (ch < 3) ? ch : ch - 3;
        const float p = (k == 0) ? g_sx[b * NN + i]
                      : (k == 1) ? g_sy[b * NN + i]
                                 : g_sz[b * NN + i];
        val = __fsub_rn(p, __ldg(&new_xyz[(b * NPOINT + j) * 3 + k]));
    } else {
        val = __ldg(&features[((size_t)b * CC + (ch - 6)) * NN + i]);
    }
    out[t] = val;
}

// ---------------------------------------------------------------------------
extern "C" void kernel_launch(void* const* d_in, const int* in_sizes, int n_in,
                              void* d_out, int out_size) {
    const float* xyz      = (const float*)d_in[0];   // (B, N, 3)
    const float* new_xyz  = (const float*)d_in[1];   // (B, NPOINT, 3)
    const float* features = (const float*)d_in[2];   // (B, C, N)
    const int*   fps_idx  = (const int*)d_in[3];     // (B, NPOINT)
    float* out = (float*)d_out;

    {
        const int n = BB * NN;
        soa_kernel<<<(n + 255) / 256, 256>>>(xyz);
    }
    {
        const int warps = BB * NPOINT;          // one warp per centroid
        const int threads = warps * 32;
        ball_query_kernel<<<(threads + 255) / 256, 256>>>(new_xyz, fps_idx);
    }
    {
        const int total = BB * TOTCH * NPOINT * NSP;
        gather_kernel<<<(total + 255) / 256, 256>>>(new_xyz, features, out);
    }
}

// round 2
// speedup vs baseline: 1.2212x; 1.2212x over previous
#include <cuda_runtime.h>
#include <cuda_bf16.h>
#include <cstdint>

#define BB 4
#define NN 8192
#define NPOINT 2048
#define CC 64
#define NS 32
#define NSP 33      // NSAMPLE + 1 (fps_idx prepended)
#define TOTCH 70    // 3 + 3 + 64

// Scratch (device globals — no allocations allowed)
__device__ int   g_idx[BB * NPOINT * NSP];
__device__ float g_sx[BB * NN];
__device__ float g_sy[BB * NN];
__device__ float g_sz[BB * NN];
__device__ float g_ft[BB * NN * CC];   // features transposed to (B, N, C)

// ---------------------------------------------------------------------------
// Kernel A: transpose xyz (B,N,3) AoS -> SoA for coalesced ball-query loads
// ---------------------------------------------------------------------------
__global__ void soa_kernel(const float* __restrict__ xyz) {
    int t = blockIdx.x * blockDim.x + threadIdx.x;
    if (t >= BB * NN) return;
    g_sx[t] = xyz[t * 3 + 0];
    g_sy[t] = xyz[t * 3 + 1];
    g_sz[t] = xyz[t * 3 + 2];
}

// ---------------------------------------------------------------------------
// Kernel A2: transpose features (B,C,N) -> (B,N,C) so per-point channel rows
// are 256B contiguous (coalesced gather reads later).
// ---------------------------------------------------------------------------
__global__ void feat_transpose_kernel(const float* __restrict__ f) {
    __shared__ float tile[32][33];
    const int n0 = blockIdx.x * 32;
    const int c0 = blockIdx.y * 32;
    const int b  = blockIdx.z;
    const int tx = threadIdx.x;      // 0..31
    const int ty = threadIdx.y;      // 0..7
    #pragma unroll
    for (int k = 0; k < 32; k += 8)
        tile[ty + k][tx] = f[((size_t)(b * CC + c0 + ty + k)) * NN + n0 + tx];
    __syncthreads();
    #pragma unroll
    for (int k = 0; k < 32; k += 8)
        g_ft[((size_t)(b * NN + n0 + ty + k)) * CC + c0 + tx] = tile[tx][ty + k];
}

// ---------------------------------------------------------------------------
// Kernel B: ball query — one warp per centroid, ballot prefix-scan collection
// ---------------------------------------------------------------------------
__global__ void ball_query_kernel(const float* __restrict__ new_xyz,
                                  const int* __restrict__ fps_idx) {
    const int lane = threadIdx.x & 31;
    const int w = (blockIdx.x * blockDim.x + threadIdx.x) >> 5;
    if (w >= BB * NPOINT) return;
    const int b = w / NPOINT;

    const float cx = __ldg(&new_xyz[w * 3 + 0]);
    const float cy = __ldg(&new_xyz[w * 3 + 1]);
    const float cz = __ldg(&new_xyz[w * 3 + 2]);
    const float r2 = __fmul_rn(0.1f, 0.1f);

    const float* __restrict__ sx = g_sx + b * NN;
    const float* __restrict__ sy = g_sy + b * NN;
    const float* __restrict__ sz = g_sz + b * NN;
    int* __restrict__ out = g_idx + w * NSP;

    int count = 0;
    int first = -1;
    const unsigned below = (1u << lane) - 1u;

    for (int base = 0; base < NN; base += 32) {
        const int i = base + lane;
        // Non-FMA, left-associated: matches XLA's (dx^2 + dy^2) + dz^2 exactly
        const float dx = __fsub_rn(cx, sx[i]);
        const float dy = __fsub_rn(cy, sy[i]);
        const float dz = __fsub_rn(cz, sz[i]);
        const float d2 = __fadd_rn(
            __fadd_rn(__fmul_rn(dx, dx), __fmul_rn(dy, dy)),
            __fmul_rn(dz, dz));
        const bool valid = d2 < r2;
        const unsigned m = __ballot_sync(0xffffffffu, valid);
        if (first < 0 && m != 0u) first = base + __ffs(m) - 1;
        if (valid) {
            const int pos = count + __popc(m & below);
            if (pos < NS) out[1 + pos] = i;
        }
        count += __popc(m);
        if (count >= NS) break;
    }

    const int pad = (first >= 0) ? first : 0;
    if (lane < NS && lane >= count) out[1 + lane] = pad;
    if (lane == 0) out[0] = fps_idx[w];
}

// ---------------------------------------------------------------------------
// Kernel C: gather + center + concat -> out (B, 70, NPOINT, 33)
// One warp per (b, j):
//   Phase A: stage 33 x 64 feature values into shared via coalesced 128B reads
//            of the transposed feature rows (stride-65 padding: conflict-free)
//   Phase B: emit all 70*33 outputs with coalesced channel-major writes
// ---------------------------------------------------------------------------
#define GW 4  // warps per block

__global__ void gather_kernel(const float* __restrict__ new_xyz,
                              float* __restrict__ out) {
    __shared__ float sh[GW][NSP * 65];     // [s][c] with stride 65
    __shared__ float cxs[GW][3][NSP];      // centered xyz
    __shared__ int   sidx[GW][NSP];

    const int wid  = threadIdx.x >> 5;
    const int lane = threadIdx.x & 31;
    const int w = blockIdx.x * GW + wid;   // (b, j) flattened
    const int b = w / NPOINT;
    const int j = w % NPOINT;

    const int* __restrict__ idxp = g_idx + w * NSP;

    // Load indices + centered xyz (33 slots; lane 0 covers s=32)
    const float ncx = __ldg(&new_xyz[w * 3 + 0]);
    const float ncy = __ldg(&new_xyz[w * 3 + 1]);
    const float ncz = __ldg(&new_xyz[w * 3 + 2]);
    for (int s = lane; s < NSP; s += 32) {
        const int i = idxp[s];
        sidx[wid][s] = i;
        cxs[wid][0][s] = __fsub_rn(g_sx[b * NN + i], ncx);
        cxs[wid][1][s] = __fsub_rn(g_sy[b * NN + i], ncy);
        cxs[wid][2][s] = __fsub_rn(g_sz[b * NN + i], ncz);
    }
    __syncwarp();

    // Phase A: coalesced feature staging (two 128B loads per neighbor row)
    for (int s = 0; s < NSP; s++) {
        const int i = sidx[wid][s];
        const float* __restrict__ fp = g_ft + ((size_t)(b * NN + i)) * CC;
        sh[wid][s * 65 + lane]      = fp[lane];
        sh[wid][s * 65 + 32 + lane] = fp[32 + lane];
    }
    __syncwarp();

    // Phase B: coalesced channel-major writes
    float* __restrict__ outb =
        out + (size_t)b * TOTCH * NPOINT * NSP + (size_t)j * NSP;
    for (int e = lane; e < TOTCH * NSP; e += 32) {
        const int ch = (e * 993) >> 15;    // == e / 33 for e < 2310
        const int s  = e - ch * 33;
        float v;
        if (ch < 6) {
            const int k = (ch < 3) ? ch : ch - 3;
            v = cxs[wid][k][s];
        } else {
            v = sh[wid][s * 65 + (ch - 6)];
        }
        outb[(size_t)ch * (NPOINT * NSP) + s] = v;
    }
}

// ---------------------------------------------------------------------------
extern "C" void kernel_launch(void* const* d_in, const int* in_sizes, int n_in,
                              void* d_out, int out_size) {
    const float* xyz      = (const float*)d_in[0];   // (B, N, 3)
    const float* new_xyz  = (const float*)d_in[1];   // (B, NPOINT, 3)
    const float* features = (const float*)d_in[2];   // (B, C, N)
    const int*   fps_idx  = (const int*)d_in[3];     // (B, NPOINT)
    float* out = (float*)d_out;

    {
        const int n = BB * NN;
        soa_kernel<<<(n + 255) / 256, 256>>>(xyz);
    }
    {
        dim3 grid(NN / 32, CC / 32, BB);
        dim3 block(32, 8);
        feat_transpose_kernel<<<grid, block>>>(features);
    }
    {
        const int warps = BB * NPOINT;
        const int threads = warps * 32;
        ball_query_kernel<<<(threads + 255) / 256, 256>>>(new_xyz, fps_idx);
    }
    {
        const int blocks = (BB * NPOINT) / GW;   // 2048
        gather_kernel<<<blocks, GW * 32>>>(new_xyz, out);
    }
}

// round 3
// speedup vs baseline: 2.6363x; 2.1589x over previous
#include <cuda_runtime.h>
#include <cuda_bf16.h>
#include <cstdint>

#define BB 4
#define NN 8192
#define NPOINT 2048
#define CC 64
#define NS 32
#define NSP 33      // NSAMPLE + 1 (fps_idx prepended)
#define TOTCH 70    // 3 + 3 + 64
#define NC1 10      // grid cells per axis (cell size = radius = 0.1)
#define NCELLS 1000
#define BUFSZ 128   // per-ball candidate buffer (expected ~34 hits; huge margin)

// Scratch (device globals — no allocations allowed)
__device__ int   g_idx[BB * NPOINT * NSP];
__device__ float g_sx[BB * NN];
__device__ float g_sy[BB * NN];
__device__ float g_sz[BB * NN];
__device__ float g_ft[BB * NN * CC];    // features transposed to (B, N, C)
__device__ int   g_cell[BB * NN];       // cell id per point (within batch)
__device__ int   g_cnt[BB * NCELLS];    // points per cell
__device__ int   g_off[BB * NCELLS];    // exclusive prefix (cell start)
__device__ int   g_cur[BB * NCELLS];    // scatter cursors
__device__ float g_gx[BB * NN];         // cell-sorted point coords
__device__ float g_gy[BB * NN];
__device__ float g_gz[BB * NN];
__device__ int   g_gi[BB * NN];         // cell-sorted original indices

// ---------------------------------------------------------------------------
// Kernel Z: zero cell counts
// ---------------------------------------------------------------------------
__global__ void zero_kernel() {
    int t = blockIdx.x * blockDim.x + threadIdx.x;
    if (t < BB * NCELLS) g_cnt[t] = 0;
}

// ---------------------------------------------------------------------------
// Kernel A: xyz AoS -> SoA, compute cell id, count per cell
// ---------------------------------------------------------------------------
__device__ __forceinline__ int cell_coord(float v) {
    int c = (int)(v * 10.0f);
    return c < 0 ? 0 : (c > 9 ? 9 : c);
}

__global__ void soa_cell_kernel(const float* __restrict__ xyz) {
    int t = blockIdx.x * blockDim.x + threadIdx.x;
    if (t >= BB * NN) return;
    const float x = xyz[t * 3 + 0];
    const float y = xyz[t * 3 + 1];
    const float z = xyz[t * 3 + 2];
    g_sx[t] = x; g_sy[t] = y; g_sz[t] = z;
    const int b = t / NN;
    const int cell = (cell_coord(z) * NC1 + cell_coord(y)) * NC1 + cell_coord(x);
    g_cell[t] = cell;
    atomicAdd(&g_cnt[b * NCELLS + cell], 1);
}

// ---------------------------------------------------------------------------
// Kernel S: exclusive scan of cell counts (one block per batch)
// ---------------------------------------------------------------------------
__global__ void scan_kernel() {
    __shared__ int sh[1024];
    const int b = blockIdx.x;
    const int t = threadIdx.x;
    const int v = (t < NCELLS) ? g_cnt[b * NCELLS + t] : 0;
    sh[t] = v;
    __syncthreads();
    for (int d = 1; d < 1024; d <<= 1) {
        const int add = (t >= d) ? sh[t - d] : 0;
        __syncthreads();
        sh[t] += add;
        __syncthreads();
    }
    if (t < NCELLS) {
        const int excl = sh[t] - v;
        g_off[b * NCELLS + t] = excl;
        g_cur[b * NCELLS + t] = excl;
    }
}

// ---------------------------------------------------------------------------
// Kernel P: scatter points into cell-sorted order
// ---------------------------------------------------------------------------
__global__ void scatter_kernel() {
    int t = blockIdx.x * blockDim.x + threadIdx.x;
    if (t >= BB * NN) return;
    const int b = t / NN;
    const int cell = g_cell[t];
    const int pos = atomicAdd(&g_cur[b * NCELLS + cell], 1);
    const int d = b * NN + pos;
    g_gx[d] = g_sx[t];
    g_gy[d] = g_sy[t];
    g_gz[d] = g_sz[t];
    g_gi[d] = t - b * NN;
}

// ---------------------------------------------------------------------------
// Kernel A2: transpose features (B,C,N) -> (B,N,C)
// ---------------------------------------------------------------------------
__global__ void feat_transpose_kernel(const float* __restrict__ f) {
    __shared__ float tile[32][33];
    const int n0 = blockIdx.x * 32;
    const int c0 = blockIdx.y * 32;
    const int b  = blockIdx.z;
    const int tx = threadIdx.x;
    const int ty = threadIdx.y;
    #pragma unroll
    for (int k = 0; k < 32; k += 8)
        tile[ty + k][tx] = f[((size_t)(b * CC + c0 + ty + k)) * NN + n0 + tx];
    __syncthreads();
    #pragma unroll
    for (int k = 0; k < 32; k += 8)
        g_ft[((size_t)(b * NN + n0 + ty + k)) * CC + c0 + tx] = tile[tx][ty + k];
}

// ---------------------------------------------------------------------------
// Kernel B: grid-accelerated ball query — one warp per centroid.
// Collect ALL in-radius hits from the 27-cell neighborhood (as 9 contiguous
// x-runs), bitonic-sort ascending by original index, keep first NS.
// Identical result to scan-order collection (smallest 32 indices; pad =
// smallest hit or 0).
// ---------------------------------------------------------------------------
#define WQ 8  // warps per block

__global__ void ball_query_grid_kernel(const float* __restrict__ new_xyz,
                                       const int* __restrict__ fps_idx) {
    __shared__ int buf[WQ][BUFSZ];

    const int lane = threadIdx.x & 31;
    const int wid  = threadIdx.x >> 5;
    const int w = blockIdx.x * WQ + wid;
    if (w >= BB * NPOINT) return;
    const int b = w / NPOINT;

    const float cx = __ldg(&new_xyz[w * 3 + 0]);
    const float cy = __ldg(&new_xyz[w * 3 + 1]);
    const float cz = __ldg(&new_xyz[w * 3 + 2]);
    const float r2 = __fmul_rn(0.1f, 0.1f);

    const int icx = cell_coord(cx);
    const int icy = cell_coord(cy);
    const int icz = cell_coord(cz);
    const int x0 = icx > 0 ? icx - 1 : 0;
    const int x1 = icx < 9 ? icx + 1 : 9;
    const int y0 = icy > 0 ? icy - 1 : 0;
    const int y1 = icy < 9 ? icy + 1 : 9;
    const int z0 = icz > 0 ? icz - 1 : 0;
    const int z1 = icz < 9 ? icz + 1 : 9;

    const unsigned below = (1u << lane) - 1u;
    int cnt = 0;

    for (int z = z0; z <= z1; z++) {
        for (int y = y0; y <= y1; y++) {
            const int rowbase = b * NCELLS + (z * NC1 + y) * NC1;
            const int start = g_off[rowbase + x0];
            const int end   = g_off[rowbase + x1] + g_cnt[rowbase + x1];
            for (int k = start; k < end; k += 32) {
                const int kk = k + lane;
                bool valid = false;
                int pi = 0;
                if (kk < end) {
                    const int d = b * NN + kk;
                    const float dx = __fsub_rn(cx, g_gx[d]);
                    const float dy = __fsub_rn(cy, g_gy[d]);
                    const float dz = __fsub_rn(cz, g_gz[d]);
                    const float d2 = __fadd_rn(
                        __fadd_rn(__fmul_rn(dx, dx), __fmul_rn(dy, dy)),
                        __fmul_rn(dz, dz));
                    valid = d2 < r2;
                    pi = g_gi[d];
                }
                const unsigned m = __ballot_sync(0xffffffffu, valid);
                if (valid) {
                    const int pos = cnt + __popc(m & below);
                    if (pos < BUFSZ) buf[wid][pos] = pi;
                }
                cnt += __popc(m);
            }
        }
    }
    if (cnt > BUFSZ) cnt = BUFSZ;

    // Pad buffer to BUFSZ with sentinel NN
    for (int t = lane; t < BUFSZ; t += 32)
        if (t >= cnt) buf[wid][t] = NN;
    __syncwarp();

    // Bitonic sort ascending (BUFSZ = 128, 64 comparators/round, 2 per lane)
    for (int k = 2; k <= BUFSZ; k <<= 1) {
        for (int j = k >> 1; j > 0; j >>= 1) {
            #pragma unroll
            for (int t = lane; t < BUFSZ / 2; t += 32) {
                const int i = ((t & ~(j - 1)) << 1) | (t & (j - 1));
                const int l = i | j;
                const int a = buf[wid][i];
                const int c = buf[wid][l];
                const bool up = ((i & k) == 0);
                if ((a > c) == up) { buf[wid][i] = c; buf[wid][l] = a; }
            }
            __syncwarp();
        }
    }

    int* __restrict__ out = g_idx + w * NSP;
    const int first = buf[wid][0];
    const int pad = (first < NN) ? first : 0;
    if (lane < NS) {
        const int v = buf[wid][lane];
        out[1 + lane] = (v < NN) ? v : pad;
    }
    if (lane == 0) out[0] = fps_idx[w];
}

// ---------------------------------------------------------------------------
// Kernel C: gather + center + concat -> out (B, 70, NPOINT, 33)
// One warp per (b, j): stage features via coalesced reads of transposed rows,
// then per-channel coalesced writes (lane = s).
// ---------------------------------------------------------------------------
#define GW 4  // warps per block

__global__ void gather_kernel(const float* __restrict__ new_xyz,
                              float* __restrict__ out) {
    __shared__ float sh[GW][NSP * 65];     // [s][c] stride 65 (conflict-free)
    __shared__ float cxs[GW][3][NSP];
    __shared__ int   sidx[GW][NSP];

    const int wid  = threadIdx.x >> 5;
    const int lane = threadIdx.x & 31;
    const int w = blockIdx.x * GW + wid;
    const int b = w / NPOINT;
    const int j = w % NPOINT;

    const int* __restrict__ idxp = g_idx + w * NSP;

    const float ncx = __ldg(&new_xyz[w * 3 + 0]);
    const float ncy = __ldg(&new_xyz[w * 3 + 1]);
    const float ncz = __ldg(&new_xyz[w * 3 + 2]);
    for (int s = lane; s < NSP; s += 32) {
        const int i = idxp[s];
        sidx[wid][s] = i;
        cxs[wid][0][s] = __fsub_rn(g_sx[b * NN + i], ncx);
        cxs[wid][1][s] = __fsub_rn(g_sy[b * NN + i], ncy);
        cxs[wid][2][s] = __fsub_rn(g_sz[b * NN + i], ncz);
    }
    __syncwarp();

    // Phase A: coalesced feature staging (two 128B loads per neighbor row)
    for (int s = 0; s < NSP; s++) {
        const int i = sidx[wid][s];
        const float* __restrict__ fp = g_ft + ((size_t)(b * NN + i)) * CC;
        sh[wid][s * 65 + lane]      = fp[lane];
        sh[wid][s * 65 + 32 + lane] = fp[32 + lane];
    }
    __syncwarp();

    // Phase B: per-channel coalesced writes; lane = s, lane 0 also covers s=32
    float* __restrict__ outb =
        out + (size_t)b * TOTCH * NPOINT * NSP + (size_t)j * NSP;
    const size_t chstr = (size_t)NPOINT * NSP;

    #pragma unroll
    for (int k = 0; k < 3; k++) {
        const float v = cxs[wid][k][lane];
        outb[(size_t)k * chstr + lane] = v;
        outb[(size_t)(k + 3) * chstr + lane] = v;
        if (lane == 0) {
            const float v32 = cxs[wid][k][32];
            outb[(size_t)k * chstr + 32] = v32;
            outb[(size_t)(k + 3) * chstr + 32] = v32;
        }
    }
    #pragma unroll 8
    for (int ch = 0; ch < CC; ch++) {
        const float v = sh[wid][lane * 65 + ch];
        float* __restrict__ row = outb + (size_t)(6 + ch) * chstr;
        row[lane] = v;
        if (lane == 0) row[32] = sh[wid][32 * 65 + ch];
    }
}

// ---------------------------------------------------------------------------
extern "C" void kernel_launch(void* const* d_in, const int* in_sizes, int n_in,
                              void* d_out, int out_size) {
    const float* xyz      = (const float*)d_in[0];   // (B, N, 3)
    const float* new_xyz  = (const float*)d_in[1];   // (B, NPOINT, 3)
    const float* features = (const float*)d_in[2];   // (B, C, N)
    const int*   fps_idx  = (const int*)d_in[3];     // (B, NPOINT)
    float* out = (float*)d_out;

    zero_kernel<<<(BB * NCELLS + 1023) / 1024, 1024>>>();
    soa_cell_kernel<<<(BB * NN + 255) / 256, 256>>>(xyz);
    {
        dim3 grid(NN / 32, CC / 32, BB);
        dim3 block(32, 8);
        feat_transpose_kernel<<<grid, block>>>(features);
    }
    scan_kernel<<<BB, 1024>>>();
    scatter_kernel<<<(BB * NN + 255) / 256, 256>>>();
    {
        const int blocks = (BB * NPOINT) / WQ;   // 1024
        ball_query_grid_kernel<<<blocks, WQ * 32>>>(new_xyz, fps_idx);
    }
    {
        const int blocks = (BB * NPOINT) / GW;   // 2048
        gather_kernel<<<blocks, GW * 32>>>(new_xyz, out);
    }
}

// round 4
// speedup vs baseline: 2.9917x; 1.1348x over previous
#include <cuda_runtime.h>
#include <cuda_bf16.h>
#include <cstdint>

#define BB 4
#define NN 8192
#define NPOINT 2048
#define CC 64
#define NS 32
#define NSP 33      // NSAMPLE + 1 (fps_idx prepended)
#define TOTCH 70    // 3 + 3 + 64
#define NC1 10      // grid cells per axis (cell size = radius = 0.1)
#define NCELLS 1000
#define BUFSZ 128   // per-ball candidate cap (expected ~34 hits; Poisson tail
                    // to 128 is ~1e-30 for this uniform input)

// Scratch (device globals — no allocations allowed)
__device__ float g_sx[BB * NN];
__device__ float g_sy[BB * NN];
__device__ float g_sz[BB * NN];
__device__ float g_ft[BB * NN * CC];    // features transposed to (B, N, C)
__device__ int   g_cell[BB * NN];
__device__ int   g_cnt[BB * NCELLS];
__device__ int   g_off[BB * NCELLS];
__device__ int   g_cur[BB * NCELLS];
__device__ float g_gx[BB * NN];         // cell-sorted coords
__device__ float g_gy[BB * NN];
__device__ float g_gz[BB * NN];
__device__ int   g_gi[BB * NN];         // cell-sorted original indices

// ---------------------------------------------------------------------------
__global__ void zero_kernel() {
    int t = blockIdx.x * blockDim.x + threadIdx.x;
    if (t < BB * NCELLS) g_cnt[t] = 0;
}

__device__ __forceinline__ int cell_coord(float v) {
    int c = (int)(v * 10.0f);
    return c < 0 ? 0 : (c > 9 ? 9 : c);
}

// xyz AoS -> SoA + cell id + per-cell count
__global__ void soa_cell_kernel(const float* __restrict__ xyz) {
    int t = blockIdx.x * blockDim.x + threadIdx.x;
    if (t >= BB * NN) return;
    const float x = xyz[t * 3 + 0];
    const float y = xyz[t * 3 + 1];
    const float z = xyz[t * 3 + 2];
    g_sx[t] = x; g_sy[t] = y; g_sz[t] = z;
    const int b = t / NN;
    const int cell = (cell_coord(z) * NC1 + cell_coord(y)) * NC1 + cell_coord(x);
    g_cell[t] = cell;
    atomicAdd(&g_cnt[b * NCELLS + cell], 1);
}

// shfl-based exclusive scan of 1000 cell counts per batch (1 block/batch)
__global__ void scan_kernel() {
    __shared__ int wsum[32];
    const int b = blockIdx.x;
    const int t = threadIdx.x;
    const int lane = t & 31;
    const int wid = t >> 5;
    const int orig = (t < NCELLS) ? g_cnt[b * NCELLS + t] : 0;
    int v = orig;
    #pragma unroll
    for (int d = 1; d < 32; d <<= 1) {
        const int n = __shfl_up_sync(0xffffffffu, v, d);
        if (lane >= d) v += n;
    }
    if (lane == 31) wsum[wid] = v;
    __syncthreads();
    if (wid == 0) {
        int s = wsum[lane];
        #pragma unroll
        for (int d = 1; d < 32; d <<= 1) {
            const int n = __shfl_up_sync(0xffffffffu, s, d);
            if (lane >= d) s += n;
        }
        wsum[lane] = s;
    }
    __syncthreads();
    const int incl = v + (wid > 0 ? wsum[wid - 1] : 0);
    if (t < NCELLS) {
        const int excl = incl - orig;
        g_off[b * NCELLS + t] = excl;
        g_cur[b * NCELLS + t] = excl;
    }
}

// scatter points into cell-sorted order
__global__ void scatter_kernel() {
    int t = blockIdx.x * blockDim.x + threadIdx.x;
    if (t >= BB * NN) return;
    const int b = t / NN;
    const int cell = g_cell[t];
    const int pos = atomicAdd(&g_cur[b * NCELLS + cell], 1);
    const int d = b * NN + pos;
    g_gx[d] = g_sx[t];
    g_gy[d] = g_sy[t];
    g_gz[d] = g_sz[t];
    g_gi[d] = t - b * NN;
}

// transpose features (B,C,N) -> (B,N,C)
__global__ void feat_transpose_kernel(const float* __restrict__ f) {
    __shared__ float tile[32][33];
    const int n0 = blockIdx.x * 32;
    const int c0 = blockIdx.y * 32;
    const int b  = blockIdx.z;
    const int tx = threadIdx.x;
    const int ty = threadIdx.y;
    #pragma unroll
    for (int k = 0; k < 32; k += 8)
        tile[ty + k][tx] = f[((size_t)(b * CC + c0 + ty + k)) * NN + n0 + tx];
    __syncthreads();
    #pragma unroll
    for (int k = 0; k < 32; k += 8)
        g_ft[((size_t)(b * NN + n0 + ty + k)) * CC + c0 + tx] = tile[tx][ty + k];
}

// ---------------------------------------------------------------------------
// Fused ball-query + gather. One warp per centroid (b, j):
//   1. Collect ALL in-radius hits from 27-cell neighborhood (9 x-runs).
//   2. Rank-select: slot of hit = #hits with smaller original index
//      (== first-NS-in-scan-order semantics; indices distinct -> ranks unique).
//   3. Gather: centered xyz from registers (lane = s); features staged in two
//      32-channel passes through a conflict-free smem tile; all output writes
//      coalesced channel-major.
// ---------------------------------------------------------------------------
#define FW 4  // warps (balls) per block

__global__ __launch_bounds__(FW * 32) void bq_gather_kernel(
        const float* __restrict__ new_xyz,
        const int* __restrict__ fps_idx,
        float* __restrict__ out) {
    __shared__ int   buf[FW][BUFSZ];
    __shared__ int   sidx[FW][NSP];
    __shared__ float tile[FW][32 * NSP];   // [c][s], stride 33: conflict-free

    const int lane = threadIdx.x & 31;
    const int wid  = threadIdx.x >> 5;
    const int w = blockIdx.x * FW + wid;
    const int b = w / NPOINT;
    const int j = w % NPOINT;

    const float cx = __ldg(&new_xyz[w * 3 + 0]);
    const float cy = __ldg(&new_xyz[w * 3 + 1]);
    const float cz = __ldg(&new_xyz[w * 3 + 2]);
    const float r2 = __fmul_rn(0.1f, 0.1f);

    // ---- 1. collect hits ----
    const int icx = cell_coord(cx), icy = cell_coord(cy), icz = cell_coord(cz);
    const int x0 = icx > 0 ? icx - 1 : 0, x1 = icx < 9 ? icx + 1 : 9;
    const int y0 = icy > 0 ? icy - 1 : 0, y1 = icy < 9 ? icy + 1 : 9;
    const int z0 = icz > 0 ? icz - 1 : 0, z1 = icz < 9 ? icz + 1 : 9;

    const unsigned below = (1u << lane) - 1u;
    int cnt = 0;

    for (int z = z0; z <= z1; z++) {
        for (int y = y0; y <= y1; y++) {
            const int rowbase = b * NCELLS + (z * NC1 + y) * NC1;
            const int start = g_off[rowbase + x0];
            const int end   = g_off[rowbase + x1] + g_cnt[rowbase + x1];
            for (int k = start; k < end; k += 32) {
                const int kk = k + lane;
                bool valid = false;
                int pi = 0;
                if (kk < end) {
                    const int d = b * NN + kk;
                    const float dx = __fsub_rn(cx, g_gx[d]);
                    const float dy = __fsub_rn(cy, g_gy[d]);
                    const float dz = __fsub_rn(cz, g_gz[d]);
                    const float d2 = __fadd_rn(
                        __fadd_rn(__fmul_rn(dx, dx), __fmul_rn(dy, dy)),
                        __fmul_rn(dz, dz));
                    valid = d2 < r2;
                    pi = g_gi[d];
                }
                const unsigned m = __ballot_sync(0xffffffffu, valid);
                if (valid) {
                    const int pos = cnt + __popc(m & below);
                    if (pos < BUFSZ) buf[wid][pos] = pi;
                }
                cnt += __popc(m);
            }
        }
    }
    if (cnt > BUFSZ) cnt = BUFSZ;
    __syncwarp();

    // ---- 2. rank-select smallest NS indices into sidx[1..NS] ----
    int vmin = 0x7fffffff;
    for (int t = lane; t < cnt; t += 32) {
        const int v = buf[wid][t];
        int rank = 0;
        for (int k = 0; k < cnt; k++) rank += (buf[wid][k] < v);
        if (rank < NS) sidx[wid][1 + rank] = v;
        if (v < vmin) vmin = v;
    }
    #pragma unroll
    for (int d = 16; d > 0; d >>= 1) {
        const int o = __shfl_xor_sync(0xffffffffu, vmin, d);
        if (o < vmin) vmin = o;
    }
    const int pad = (cnt > 0) ? vmin : 0;
    if (lane < NS && lane >= cnt) sidx[wid][1 + lane] = pad;
    if (lane == 0) sidx[wid][0] = fps_idx[w];
    __syncwarp();

    // ---- 3. gather ----
    float* __restrict__ outb =
        out + (size_t)b * TOTCH * NPOINT * NSP + (size_t)j * NSP;
    const size_t chstr = (size_t)NPOINT * NSP;

    // centered xyz: lane handles s = lane; lane 0 also s = 32
    {
        const int i = sidx[wid][lane];
        const float vx = __fsub_rn(g_sx[b * NN + i], cx);
        const float vy = __fsub_rn(g_sy[b * NN + i], cy);
        const float vz = __fsub_rn(g_sz[b * NN + i], cz);
        outb[0 * chstr + lane] = vx;
        outb[1 * chstr + lane] = vy;
        outb[2 * chstr + lane] = vz;
        outb[3 * chstr + lane] = vx;
        outb[4 * chstr + lane] = vy;
        outb[5 * chstr + lane] = vz;
        if (lane == 0) {
            const int i32 = sidx[wid][32];
            const float wx = __fsub_rn(g_sx[b * NN + i32], cx);
            const float wy = __fsub_rn(g_sy[b * NN + i32], cy);
            const float wz = __fsub_rn(g_sz[b * NN + i32], cz);
            outb[0 * chstr + 32] = wx;
            outb[1 * chstr + 32] = wy;
            outb[2 * chstr + 32] = wz;
            outb[3 * chstr + 32] = wx;
            outb[4 * chstr + 32] = wy;
            outb[5 * chstr + 32] = wz;
        }
    }

    // features: two 32-channel passes; per-s coalesced 128B reads into tile,
    // per-channel coalesced writes out
    #pragma unroll
    for (int p = 0; p < 2; p++) {
        #pragma unroll 8
        for (int s = 0; s < NSP; s++) {
            const int i = sidx[wid][s];
            tile[wid][lane * NSP + s] =
                g_ft[((size_t)(b * NN + i)) * CC + p * 32 + lane];
        }
        __syncwarp();
        #pragma unroll 8
        for (int c = 0; c < 32; c++) {
            float* __restrict__ row = outb + (size_t)(6 + p * 32 + c) * chstr;
            row[lane] = tile[wid][c * NSP + lane];
            if (lane == 0) row[32] = tile[wid][c * NSP + 32];
        }
        __syncwarp();
    }
}

// ---------------------------------------------------------------------------
extern "C" void kernel_launch(void* const* d_in, const int* in_sizes, int n_in,
                              void* d_out, int out_size) {
    const float* xyz      = (const float*)d_in[0];   // (B, N, 3)
    const float* new_xyz  = (const float*)d_in[1];   // (B, NPOINT, 3)
    const float* features = (const float*)d_in[2];   // (B, C, N)
    const int*   fps_idx  = (const int*)d_in[3];     // (B, NPOINT)
    float* out = (float*)d_out;

    zero_kernel<<<(BB * NCELLS + 1023) / 1024, 1024>>>();
    soa_cell_kernel<<<(BB * NN + 255) / 256, 256>>>(xyz);
    {
        dim3 grid(NN / 32, CC / 32, BB);
        dim3 block(32, 8);
        feat_transpose_kernel<<<grid, block>>>(features);
    }
    scan_kernel<<<BB, 1024>>>();
    scatter_kernel<<<(BB * NN + 255) / 256, 256>>>();
    {
        const int blocks = (BB * NPOINT) / FW;   // 2048
        bq_gather_kernel<<<blocks, FW * 32>>>(new_xyz, fps_idx, out);
    }
}

// round 5
// speedup vs baseline: 3.7320x; 1.2474x over previous
#include <cuda_runtime.h>
#include <cuda_bf16.h>
#include <cstdint>

#define BB 4
#define NN 8192
#define NPOINT 2048
#define CC 64
#define NS 32
#define NSP 33      // NSAMPLE + 1 (fps_idx prepended)
#define TOTCH 70    // 3 + 3 + 64
#define NC1 10      // grid cells per axis (cell size = radius = 0.1)
#define NCELLS 1000
#define BUFSZ 128   // per-ball candidate cap (expected ~34 hits)

// Scratch (device globals — no allocations allowed)
__device__ float4 g_p4[BB * NN];        // xyz AoS (w unused) by original index
__device__ int    g_cell[BB * NN];
__device__ int    g_off[BB * NCELLS];   // cell start (exclusive prefix)
__device__ int    g_end[BB * NCELLS];   // cell end
__device__ float4 g_g4[BB * NN];        // cell-sorted (x,y,z, idx-as-float-bits)
__device__ float  g_ft[BB * NN * CC];   // features transposed to (B, N, C)

// ---------------------------------------------------------------------------
__device__ __forceinline__ int cell_coord(float v) {
    int c = (int)(v * 10.0f);
    return c < 0 ? 0 : (c > 9 ? 9 : c);
}

// Kernel 1: xyz AoS -> packed float4 + cell id (no atomics)
__global__ void prep_kernel(const float* __restrict__ xyz) {
    int t = blockIdx.x * blockDim.x + threadIdx.x;
    if (t >= BB * NN) return;
    const float x = xyz[t * 3 + 0];
    const float y = xyz[t * 3 + 1];
    const float z = xyz[t * 3 + 2];
    g_p4[t] = make_float4(x, y, z, 0.0f);
    g_cell[t] = (cell_coord(z) * NC1 + cell_coord(y)) * NC1 + cell_coord(x);
}

// Kernel 2: transpose features (B,C,N) -> (B,N,C)
__global__ void feat_transpose_kernel(const float* __restrict__ f) {
    __shared__ float tile[32][33];
    const int n0 = blockIdx.x * 32;
    const int c0 = blockIdx.y * 32;
    const int b  = blockIdx.z;
    const int tx = threadIdx.x;
    const int ty = threadIdx.y;
    #pragma unroll
    for (int k = 0; k < 32; k += 8)
        tile[ty + k][tx] = f[((size_t)(b * CC + c0 + ty + k)) * NN + n0 + tx];
    __syncthreads();
    #pragma unroll
    for (int k = 0; k < 32; k += 8)
        g_ft[((size_t)(b * NN + n0 + ty + k)) * CC + c0 + tx] = tile[tx][ty + k];
}

// Kernel 3: grid build — one block per batch. Fuses histogram (smem, no
// global zeroing), exclusive scan (shfl), and cell-sorted scatter (smem
// cursors). Within-cell order is arbitrary: rank-select later sorts by
// original index, so semantics are preserved.
__global__ __launch_bounds__(1024) void grid_build_kernel() {
    __shared__ int hist[NCELLS];
    __shared__ int wsum[32];
    const int b = blockIdx.x;
    const int t = threadIdx.x;
    const int lane = t & 31;
    const int wid = t >> 5;

    if (t < NCELLS) hist[t] = 0;
    __syncthreads();

    #pragma unroll
    for (int p = t; p < NN; p += 1024)
        atomicAdd(&hist[g_cell[b * NN + p]], 1);
    __syncthreads();

    const int orig = (t < NCELLS) ? hist[t] : 0;
    int v = orig;
    #pragma unroll
    for (int d = 1; d < 32; d <<= 1) {
        const int n = __shfl_up_sync(0xffffffffu, v, d);
        if (lane >= d) v += n;
    }
    if (lane == 31) wsum[wid] = v;
    __syncthreads();
    if (wid == 0) {
        int s = wsum[lane];
        #pragma unroll
        for (int d = 1; d < 32; d <<= 1) {
            const int n = __shfl_up_sync(0xffffffffu, s, d);
            if (lane >= d) s += n;
        }
        wsum[lane] = s;
    }
    __syncthreads();
    const int excl = v - orig + (wid > 0 ? wsum[wid - 1] : 0);
    if (t < NCELLS) {
        g_off[b * NCELLS + t] = excl;
        g_end[b * NCELLS + t] = excl + orig;
    }
    __syncthreads();
    if (t < NCELLS) hist[t] = excl;     // becomes scatter cursor
    __syncthreads();

    for (int p = t; p < NN; p += 1024) {
        const int cell = g_cell[b * NN + p];
        const int pos = atomicAdd(&hist[cell], 1);
        float4 q = g_p4[b * NN + p];
        q.w = __int_as_float(p);
        g_g4[b * NN + pos] = q;
    }
}

// ---------------------------------------------------------------------------
// Kernel 4: fused ball-query + gather. One warp per centroid (b, j).
//   1. Collect ALL in-radius hits in 27-cell neighborhood (9 x-runs,
//      1 LDG.128 per candidate).
//   2. Rank-select smallest NS original indices (== scan-order semantics).
//   3. Gather: centered xyz via float4; features in 4 passes of 16 channels
//      through a small conflict-free smem tile; coalesced channel-major out.
// ---------------------------------------------------------------------------
#define FW 4  // warps (balls) per block

__global__ __launch_bounds__(FW * 32, 16) void bq_gather_kernel(
        const float* __restrict__ new_xyz,
        const int* __restrict__ fps_idx,
        float* __restrict__ out) {
    __shared__ unsigned short buf[FW][BUFSZ];
    __shared__ int   sidx[FW][NSP];
    __shared__ float tile[FW][16 * NSP];   // [c][s] stride 33, 16 channels

    const int lane = threadIdx.x & 31;
    const int wid  = threadIdx.x >> 5;
    const int w = blockIdx.x * FW + wid;
    const int b = w / NPOINT;
    const int j = w % NPOINT;

    const float cx = __ldg(&new_xyz[w * 3 + 0]);
    const float cy = __ldg(&new_xyz[w * 3 + 1]);
    const float cz = __ldg(&new_xyz[w * 3 + 2]);
    const float r2 = __fmul_rn(0.1f, 0.1f);

    // ---- 1. collect hits ----
    const int icx = cell_coord(cx), icy = cell_coord(cy), icz = cell_coord(cz);
    const int x0 = icx > 0 ? icx - 1 : 0, x1 = icx < 9 ? icx + 1 : 9;
    const int y0 = icy > 0 ? icy - 1 : 0, y1 = icy < 9 ? icy + 1 : 9;
    const int z0 = icz > 0 ? icz - 1 : 0, z1 = icz < 9 ? icz + 1 : 9;

    const unsigned below = (1u << lane) - 1u;
    int cnt = 0;

    for (int z = z0; z <= z1; z++) {
        for (int y = y0; y <= y1; y++) {
            const int rowbase = b * NCELLS + (z * NC1 + y) * NC1;
            const int start = g_off[rowbase + x0];
            const int end   = g_end[rowbase + x1];
            for (int k = start; k < end; k += 32) {
                const int kk = k + lane;
                bool valid = false;
                int pi = 0;
                if (kk < end) {
                    const float4 p = g_g4[b * NN + kk];
                    const float dx = __fsub_rn(cx, p.x);
                    const float dy = __fsub_rn(cy, p.y);
                    const float dz = __fsub_rn(cz, p.z);
                    const float d2 = __fadd_rn(
                        __fadd_rn(__fmul_rn(dx, dx), __fmul_rn(dy, dy)),
                        __fmul_rn(dz, dz));
                    valid = d2 < r2;
                    pi = __float_as_int(p.w);
                }
                const unsigned m = __ballot_sync(0xffffffffu, valid);
                if (valid) {
                    const int pos = cnt + __popc(m & below);
                    if (pos < BUFSZ) buf[wid][pos] = (unsigned short)pi;
                }
                cnt += __popc(m);
            }
        }
    }
    if (cnt > BUFSZ) cnt = BUFSZ;
    __syncwarp();

    // ---- 2. rank-select smallest NS indices into sidx[1..NS] ----
    int vmin = 0x7fffffff;
    for (int t = lane; t < cnt; t += 32) {
        const int v = buf[wid][t];
        int rank = 0;
        for (int k = 0; k < cnt; k++) rank += (buf[wid][k] < v);
        if (rank < NS) sidx[wid][1 + rank] = v;
        if (v < vmin) vmin = v;
    }
    #pragma unroll
    for (int d = 16; d > 0; d >>= 1) {
        const int o = __shfl_xor_sync(0xffffffffu, vmin, d);
        if (o < vmin) vmin = o;
    }
    const int pad = (cnt > 0) ? vmin : 0;
    if (lane < NS && lane >= cnt) sidx[wid][1 + lane] = pad;
    if (lane == 0) sidx[wid][0] = fps_idx[w];
    __syncwarp();

    // ---- 3. gather ----
    float* __restrict__ outb =
        out + (size_t)b * TOTCH * NPOINT * NSP + (size_t)j * NSP;
    const size_t chstr = (size_t)NPOINT * NSP;

    // centered xyz (lane = s; lane 0 also covers s = 32)
    {
        const int i = sidx[wid][lane];
        const float4 p = g_p4[b * NN + i];
        const float vx = __fsub_rn(p.x, cx);
        const float vy = __fsub_rn(p.y, cy);
        const float vz = __fsub_rn(p.z, cz);
        outb[0 * chstr + lane] = vx;
        outb[1 * chstr + lane] = vy;
        outb[2 * chstr + lane] = vz;
        outb[3 * chstr + lane] = vx;
        outb[4 * chstr + lane] = vy;
        outb[5 * chstr + lane] = vz;
        if (lane == 0) {
            const int i32 = sidx[wid][32];
            const float4 q = g_p4[b * NN + i32];
            const float wx = __fsub_rn(q.x, cx);
            const float wy = __fsub_rn(q.y, cy);
            const float wz = __fsub_rn(q.z, cz);
            outb[0 * chstr + 32] = wx;
            outb[1 * chstr + 32] = wy;
            outb[2 * chstr + 32] = wz;
            outb[3 * chstr + 32] = wx;
            outb[4 * chstr + 32] = wy;
            outb[5 * chstr + 32] = wz;
        }
    }

    // features: 4 passes x 16 channels; half-warp per s (64B coalesced reads)
    const int c  = lane & 15;
    const int sh = lane >> 4;
    #pragma unroll
    for (int p = 0; p < 4; p++) {
        const int cbase = p * 16;
        #pragma unroll
        for (int s = 0; s < 32; s += 2) {
            const int i = sidx[wid][s + sh];
            tile[wid][c * NSP + s + sh] =
                g_ft[((size_t)(b * NN + i)) * CC + cbase + c];
        }
        if (sh == 0) {
            const int i = sidx[wid][32];
            tile[wid][c * NSP + 32] =
                g_ft[((size_t)(b * NN + i)) * CC + cbase + c];
        }
        __syncwarp();
        #pragma unroll
        for (int c2 = 0; c2 < 16; c2++) {
            float* __restrict__ row = outb + (size_t)(6 + cbase + c2) * chstr;
            row[lane] = tile[wid][c2 * NSP + lane];
            if (lane == 0) row[32] = tile[wid][c2 * NSP + 32];
        }
        __syncwarp();
    }
}

// ---------------------------------------------------------------------------
extern "C" void kernel_launch(void* const* d_in, const int* in_sizes, int n_in,
                              void* d_out, int out_size) {
    const float* xyz      = (const float*)d_in[0];   // (B, N, 3)
    const float* new_xyz  = (const float*)d_in[1];   // (B, NPOINT, 3)
    const float* features = (const float*)d_in[2];   // (B, C, N)
    const int*   fps_idx  = (const int*)d_in[3];     // (B, NPOINT)
    float* out = (float*)d_out;

    prep_kernel<<<(BB * NN + 255) / 256, 256>>>(xyz);
    {
        dim3 grid(NN / 32, CC / 32, BB);
        dim3 block(32, 8);
        feat_transpose_kernel<<<grid, block>>>(features);
    }
    grid_build_kernel<<<BB, 1024>>>();
    {
        const int blocks = (BB * NPOINT) / FW;   // 2048
        bq_gather_kernel<<<blocks, FW * 32>>>(new_xyz, fps_idx, out);
    }
}

// round 6
// speedup vs baseline: 3.7368x; 1.0013x over previous
#include <cuda_runtime.h>
#include <cuda_bf16.h>
#include <cstdint>

#define BB 4
#define NN 8192
#define NPOINT 2048
#define CC 64
#define NS 32
#define NSP 33      // NSAMPLE + 1 (fps_idx prepended)
#define TOTCH 70    // 3 + 3 + 64
#define NC1 10      // grid cells per axis (cell size = radius = 0.1)
#define NCELLS 1000
#define BUFSZ 128   // per-ball candidate cap (expected ~34 hits)

// Scratch (device globals — no allocations allowed)
__device__ float4 g_p4[BB * NN];        // xyz by original index (w unused)
__device__ int    g_off[BB * NCELLS];   // cell start
__device__ int    g_end[BB * NCELLS];   // cell end
__device__ float4 g_g4[BB * NN];        // cell-sorted (x,y,z, idx-bits)
__device__ float4 g_ft4[BB * NN * (CC / 4)];  // features (B,N,C) as float4

// ---------------------------------------------------------------------------
__device__ __forceinline__ int cell_coord(float v) {
    int c = (int)(v * 10.0f);
    return c < 0 ? 0 : (c > 9 ? 9 : c);
}

// Kernel 1: transpose features (B,C,N) -> (B,N,C)
__global__ void feat_transpose_kernel(const float* __restrict__ f) {
    __shared__ float tile[32][33];
    const int n0 = blockIdx.x * 32;
    const int c0 = blockIdx.y * 32;
    const int b  = blockIdx.z;
    const int tx = threadIdx.x;
    const int ty = threadIdx.y;
    float* __restrict__ ft = (float*)g_ft4;
    #pragma unroll
    for (int k = 0; k < 32; k += 8)
        tile[ty + k][tx] = f[((size_t)(b * CC + c0 + ty + k)) * NN + n0 + tx];
    __syncthreads();
    #pragma unroll
    for (int k = 0; k < 32; k += 8)
        ft[((size_t)(b * NN + n0 + ty + k)) * CC + c0 + tx] = tile[tx][ty + k];
}

// Kernel 2: fused prep + grid build — one block per batch.
// Pass 1: read xyz AoS -> g_p4, cell ids into smem (u16), smem histogram.
// Then: shfl scan -> g_off/g_end; Pass 2: scatter via smem cursors -> g_g4.
__global__ __launch_bounds__(1024) void grid_build_kernel(
        const float* __restrict__ xyz) {
    __shared__ unsigned short cell16[NN];
    __shared__ int hist[NCELLS];
    __shared__ int wsum[32];
    const int b = blockIdx.x;
    const int t = threadIdx.x;
    const int lane = t & 31;
    const int wid = t >> 5;

    if (t < NCELLS) hist[t] = 0;
    __syncthreads();

    for (int p = t; p < NN; p += 1024) {
        const float x = xyz[(b * NN + p) * 3 + 0];
        const float y = xyz[(b * NN + p) * 3 + 1];
        const float z = xyz[(b * NN + p) * 3 + 2];
        g_p4[b * NN + p] = make_float4(x, y, z, 0.0f);
        const int cell =
            (cell_coord(z) * NC1 + cell_coord(y)) * NC1 + cell_coord(x);
        cell16[p] = (unsigned short)cell;
        atomicAdd(&hist[cell], 1);
    }
    __syncthreads();

    const int orig = (t < NCELLS) ? hist[t] : 0;
    int v = orig;
    #pragma unroll
    for (int d = 1; d < 32; d <<= 1) {
        const int n = __shfl_up_sync(0xffffffffu, v, d);
        if (lane >= d) v += n;
    }
    if (lane == 31) wsum[wid] = v;
    __syncthreads();
    if (wid == 0) {
        int s = wsum[lane];
        #pragma unroll
        for (int d = 1; d < 32; d <<= 1) {
            const int n = __shfl_up_sync(0xffffffffu, s, d);
            if (lane >= d) s += n;
        }
        wsum[lane] = s;
    }
    __syncthreads();
    const int excl = v - orig + (wid > 0 ? wsum[wid - 1] : 0);
    if (t < NCELLS) {
        g_off[b * NCELLS + t] = excl;
        g_end[b * NCELLS + t] = excl + orig;
    }
    __syncthreads();
    if (t < NCELLS) hist[t] = excl;     // becomes scatter cursor
    __syncthreads();

    for (int p = t; p < NN; p += 1024) {
        const int cell = cell16[p];
        const int pos = atomicAdd(&hist[cell], 1);
        float4 q = g_p4[b * NN + p];
        q.w = __int_as_float(p);
        g_g4[b * NN + pos] = q;
    }
}

// ---------------------------------------------------------------------------
// Kernel 3: fused ball-query + gather. Block = 4 warps = 4 ADJACENT balls
// (same batch). Per warp: collect hits (27-cell neighborhood, LDG.128),
// rank-select smallest NS (== scan-order), stage centered xyz + features.
// Block-cooperative output writes: per channel, the block's 4 rows form one
// 528B contiguous span (halves write wavefronts vs per-ball rows).
// ---------------------------------------------------------------------------
#define FW 4

__global__ __launch_bounds__(FW * 32, 12) void bq_gather_kernel(
        const float* __restrict__ new_xyz,
        const int* __restrict__ fps_idx,
        float* __restrict__ out) {
    __shared__ float s_tile[FW][33 * 33];  // [s*33+c], c<32; aliased as buf
    __shared__ int   s_sidx[FW][NSP];
    __shared__ float s_cxs[FW][3][NSP];

    const int tid  = threadIdx.x;
    const int lane = tid & 31;
    const int wid  = tid >> 5;
    const int w = blockIdx.x * FW + wid;
    const int b = w / NPOINT;
    const int j0 = (blockIdx.x * FW) % NPOINT;   // block's first ball

    const float cx = __ldg(&new_xyz[w * 3 + 0]);
    const float cy = __ldg(&new_xyz[w * 3 + 1]);
    const float cz = __ldg(&new_xyz[w * 3 + 2]);
    const float r2 = __fmul_rn(0.1f, 0.1f);

    // ---- Phase A: collection (buf aliases this warp's tile) ----
    unsigned short* buf = (unsigned short*)&s_tile[wid][0];

    const int icx = cell_coord(cx), icy = cell_coord(cy), icz = cell_coord(cz);
    const int x0 = icx > 0 ? icx - 1 : 0, x1 = icx < 9 ? icx + 1 : 9;
    const int y0 = icy > 0 ? icy - 1 : 0, y1 = icy < 9 ? icy + 1 : 9;
    const int z0 = icz > 0 ? icz - 1 : 0, z1 = icz < 9 ? icz + 1 : 9;

    const unsigned below = (1u << lane) - 1u;
    int cnt = 0;

    for (int z = z0; z <= z1; z++) {
        for (int y = y0; y <= y1; y++) {
            const int rowbase = b * NCELLS + (z * NC1 + y) * NC1;
            const int start = g_off[rowbase + x0];
            const int end   = g_end[rowbase + x1];
            for (int k = start; k < end; k += 32) {
                const int kk = k + lane;
                bool valid = false;
                int pi = 0;
                if (kk < end) {
                    const float4 p = g_g4[b * NN + kk];
                    const float dx = __fsub_rn(cx, p.x);
                    const float dy = __fsub_rn(cy, p.y);
                    const float dz = __fsub_rn(cz, p.z);
                    const float d2 = __fadd_rn(
                        __fadd_rn(__fmul_rn(dx, dx), __fmul_rn(dy, dy)),
                        __fmul_rn(dz, dz));
                    valid = d2 < r2;
                    pi = __float_as_int(p.w);
                }
                const unsigned m = __ballot_sync(0xffffffffu, valid);
                if (valid) {
                    const int pos = cnt + __popc(m & below);
                    if (pos < BUFSZ) buf[pos] = (unsigned short)pi;
                }
                cnt += __popc(m);
            }
        }
    }
    if (cnt > BUFSZ) cnt = BUFSZ;
    __syncwarp();

    // rank-select smallest NS into sidx[1..NS]
    int vmin = 0x7fffffff;
    for (int t = lane; t < cnt; t += 32) {
        const int v = buf[t];
        int rank = 0;
        for (int k = 0; k < cnt; k++) rank += (buf[k] < v);
        if (rank < NS) s_sidx[wid][1 + rank] = v;
        if (v < vmin) vmin = v;
    }
    #pragma unroll
    for (int d = 16; d > 0; d >>= 1) {
        const int o = __shfl_xor_sync(0xffffffffu, vmin, d);
        if (o < vmin) vmin = o;
    }
    const int pad = (cnt > 0) ? vmin : 0;
    if (lane < NS && lane >= cnt) s_sidx[wid][1 + lane] = pad;
    if (lane == 0) s_sidx[wid][0] = fps_idx[w];
    __syncwarp();

    // centered xyz into smem (lane = s; lane 0 also s = 32)
    {
        const int i = s_sidx[wid][lane];
        const float4 p = g_p4[b * NN + i];
        s_cxs[wid][0][lane] = __fsub_rn(p.x, cx);
        s_cxs[wid][1][lane] = __fsub_rn(p.y, cy);
        s_cxs[wid][2][lane] = __fsub_rn(p.z, cz);
        if (lane == 0) {
            const int i32 = s_sidx[wid][32];
            const float4 q = g_p4[b * NN + i32];
            s_cxs[wid][0][32] = __fsub_rn(q.x, cx);
            s_cxs[wid][1][32] = __fsub_rn(q.y, cy);
            s_cxs[wid][2][32] = __fsub_rn(q.z, cz);
        }
    }
    __syncthreads();

    // ---- Phase B: cooperative output ----
    const size_t chstr = (size_t)NPOINT * NSP;
    float* __restrict__ outb0 =
        out + ((size_t)b * TOTCH * NPOINT + j0) * NSP;

    // xyz channels 0..5 (block-cooperative, 528B contiguous per channel)
    #pragma unroll
    for (int k = 0; k < 6; k++) {
        const int k3 = (k < 3) ? k : k - 3;
        float* __restrict__ dst = outb0 + (size_t)k * chstr;
        {
            const int e = tid;                    // 0..127
            const int w4 = (e * 993) >> 15;       // e / 33
            const int s  = e - w4 * 33;
            dst[e] = s_cxs[w4][k3][s];
        }
        if (tid < 4) dst[128 + tid] = s_cxs[3][k3][29 + tid];
    }

    // features: 2 passes x 32 channels
    const int ls = lane >> 3, c4 = lane & 7;
    #pragma unroll
    for (int p = 0; p < 2; p++) {
        // staging: full 128B line per s (float4 per lane), conflict-free STS
        const float4* __restrict__ ftb =
            g_ft4 + (size_t)(b * NN) * 16 + p * 8 + c4;
        #pragma unroll
        for (int s0 = 0; s0 < 32; s0 += 4) {
            const int s = s0 + ls;
            const int i = s_sidx[wid][s];
            const float4 v = ftb[(size_t)i * 16];
            float* tw = &s_tile[wid][s * 33 + c4 * 4];
            tw[0] = v.x; tw[1] = v.y; tw[2] = v.z; tw[3] = v.w;
        }
        if (lane < 8) {
            const int i = s_sidx[wid][32];
            const float4 v = g_ft4[((size_t)(b * NN + i)) * 16 + p * 8 + lane];
            float* tw = &s_tile[wid][32 * 33 + lane * 4];
            tw[0] = v.x; tw[1] = v.y; tw[2] = v.z; tw[3] = v.w;
        }
        __syncthreads();

        // cooperative writes: 528B contiguous per channel
        const int e = tid;
        const int w4 = (e * 993) >> 15;
        const int s  = e - w4 * 33;
        #pragma unroll 8
        for (int c = 0; c < 32; c++) {
            float* __restrict__ dst = outb0 + (size_t)(6 + p * 32 + c) * chstr;
            dst[e] = s_tile[w4][s * 33 + c];
            if (tid < 4) dst[128 + tid] = s_tile[3][(29 + tid) * 33 + c];
        }
        __syncthreads();
    }
}

// ---------------------------------------------------------------------------
extern "C" void kernel_launch(void* const* d_in, const int* in_sizes, int n_in,
                              void* d_out, int out_size) {
    const float* xyz      = (const float*)d_in[0];   // (B, N, 3)
    const float* new_xyz  = (const float*)d_in[1];   // (B, NPOINT, 3)
    const float* features = (const float*)d_in[2];   // (B, C, N)
    const int*   fps_idx  = (const int*)d_in[3];     // (B, NPOINT)
    float* out = (float*)d_out;

    {
        dim3 grid(NN / 32, CC / 32, BB);
        dim3 block(32, 8);
        feat_transpose_kernel<<<grid, block>>>(features);
    }
    grid_build_kernel<<<BB, 1024>>>(xyz);
    {
        const int blocks = (BB * NPOINT) / FW;   // 2048
        bq_gather_kernel<<<blocks, FW * 32>>>(new_xyz, fps_idx, out);
    }
}

// round 7
// speedup vs baseline: 3.7659x; 1.0078x over previous
#include <cuda_runtime.h>
#include <cuda_bf16.h>
#include <cstdint>

#define BB 4
#define NN 8192
#define NPOINT 2048
#define CC 64
#define NS 32
#define NSP 33      // NSAMPLE + 1 (fps_idx prepended)
#define TOTCH 70    // 3 + 3 + 64
#define NC1 10      // grid cells per axis (cell size = radius = 0.1)
#define NCELLS 1000
#define BUFSZ 128   // per-ball candidate cap (expected ~34 hits)

// Scratch (device globals — no allocations allowed)
__device__ float4 g_p4[BB * NN];        // xyz by original index (w unused)
__device__ int    g_off[BB * NCELLS];   // cell start
__device__ int    g_end[BB * NCELLS];   // cell end
__device__ float4 g_g4[BB * NN];        // cell-sorted (x,y,z, idx-bits)
__device__ float4 g_ft4[BB * NN * (CC / 4)];  // features (B,N,C) as float4

// ---------------------------------------------------------------------------
__device__ __forceinline__ int cell_coord(float v) {
    int c = (int)(v * 10.0f);
    return c < 0 ? 0 : (c > 9 ? 9 : c);
}

// Kernel 1: transpose features (B,C,N) -> (B,N,C), float4 both sides.
// Block: 256 threads, one 32c x 32n tile.
__global__ void feat_transpose_kernel(const float* __restrict__ f) {
    __shared__ float tile[32][33];
    const int n0 = blockIdx.x * 32;
    const int c0 = blockIdx.y * 32;
    const int b  = blockIdx.z;
    const int t  = threadIdx.x;

    // Load: thread t -> c = t/8, n4 = t%8 (LDG.128 along n)
    {
        const int c = t >> 3, n4 = t & 7;
        const float4 v = *(const float4*)
            &f[((size_t)(b * CC + c0 + c)) * NN + n0 + n4 * 4];
        float* tw = &tile[c][n4 * 4];
        tw[0] = v.x; tw[1] = v.y; tw[2] = v.z; tw[3] = v.w;
    }
    __syncthreads();

    // Store: thread t -> n = t/8, c4 = t%8 (STG.128 along c)
    {
        const int n = t >> 3, c4 = t & 7;
        float4 v;
        v.x = tile[c4 * 4 + 0][n];
        v.y = tile[c4 * 4 + 1][n];
        v.z = tile[c4 * 4 + 2][n];
        v.w = tile[c4 * 4 + 3][n];
        *(float4*)((float*)g_ft4 +
                   ((size_t)(b * NN + n0 + n)) * CC + c0 + c4 * 4) = v;
    }
}

// Kernel 2: fused prep + grid build — one block per batch.
__global__ __launch_bounds__(1024) void grid_build_kernel(
        const float* __restrict__ xyz) {
    __shared__ unsigned short cell16[NN];
    __shared__ int hist[NCELLS];
    __shared__ int wsum[32];
    const int b = blockIdx.x;
    const int t = threadIdx.x;
    const int lane = t & 31;
    const int wid = t >> 5;

    if (t < NCELLS) hist[t] = 0;
    __syncthreads();

    for (int p = t; p < NN; p += 1024) {
        const float x = xyz[(b * NN + p) * 3 + 0];
        const float y = xyz[(b * NN + p) * 3 + 1];
        const float z = xyz[(b * NN + p) * 3 + 2];
        g_p4[b * NN + p] = make_float4(x, y, z, 0.0f);
        const int cell =
            (cell_coord(z) * NC1 + cell_coord(y)) * NC1 + cell_coord(x);
        cell16[p] = (unsigned short)cell;
        atomicAdd(&hist[cell], 1);
    }
    __syncthreads();

    const int orig = (t < NCELLS) ? hist[t] : 0;
    int v = orig;
    #pragma unroll
    for (int d = 1; d < 32; d <<= 1) {
        const int n = __shfl_up_sync(0xffffffffu, v, d);
        if (lane >= d) v += n;
    }
    if (lane == 31) wsum[wid] = v;
    __syncthreads();
    if (wid == 0) {
        int s = wsum[lane];
        #pragma unroll
        for (int d = 1; d < 32; d <<= 1) {
            const int n = __shfl_up_sync(0xffffffffu, s, d);
            if (lane >= d) s += n;
        }
        wsum[lane] = s;
    }
    __syncthreads();
    const int excl = v - orig + (wid > 0 ? wsum[wid - 1] : 0);
    if (t < NCELLS) {
        g_off[b * NCELLS + t] = excl;
        g_end[b * NCELLS + t] = excl + orig;
    }
    __syncthreads();
    if (t < NCELLS) hist[t] = excl;
    __syncthreads();

    for (int p = t; p < NN; p += 1024) {
        const int cell = cell16[p];
        const int pos = atomicAdd(&hist[cell], 1);
        float4 q = g_p4[b * NN + p];
        q.w = __int_as_float(p);
        g_g4[b * NN + pos] = q;
    }
}

// ---------------------------------------------------------------------------
// Kernel 3: fused ball-query + gather. Block = 4 warps = 4 ADJACENT balls.
// smem ~10.6KB -> 16 blocks/SM (64 warps, full occupancy).
// Phase B: 4 passes x 16 channels; block-wide tile [ch][132] so each output
// channel row is 33 aligned float4 -> LDS.128 + STG.128.
// ---------------------------------------------------------------------------
#define FW 4
#define PCH 16                       // channels per pass
#define TROW 132                     // 4 balls * 33 slots

__global__ __launch_bounds__(FW * 32, 16) void bq_gather_kernel(
        const float* __restrict__ new_xyz,
        const int* __restrict__ fps_idx,
        float* __restrict__ out) {
    __shared__ float s_tile[PCH * TROW];   // [ch][132]; head aliased as buf
    __shared__ int   s_sidx[FW][NSP];
    __shared__ float s_cxs[FW][3][NSP];

    const int tid  = threadIdx.x;
    const int lane = tid & 31;
    const int wid  = tid >> 5;
    const int w = blockIdx.x * FW + wid;
    const int b = w / NPOINT;
    const int j0 = (blockIdx.x * FW) % NPOINT;

    const float cx = __ldg(&new_xyz[w * 3 + 0]);
    const float cy = __ldg(&new_xyz[w * 3 + 1]);
    const float cz = __ldg(&new_xyz[w * 3 + 2]);
    const float r2 = __fmul_rn(0.1f, 0.1f);

    // per-warp candidate buffer aliases the tile (disjoint phases)
    unsigned short* buf = (unsigned short*)s_tile + wid * BUFSZ;

    // ---- Phase A: collection ----
    const int icx = cell_coord(cx), icy = cell_coord(cy), icz = cell_coord(cz);
    const int x0 = icx > 0 ? icx - 1 : 0, x1 = icx < 9 ? icx + 1 : 9;
    const int y0 = icy > 0 ? icy - 1 : 0, y1 = icy < 9 ? icy + 1 : 9;
    const int z0 = icz > 0 ? icz - 1 : 0, z1 = icz < 9 ? icz + 1 : 9;
    const int ny = y1 - y0 + 1;
    const int nrows = (z1 - z0 + 1) * ny;

    // lane-parallel prefetch of the <=9 row ranges, broadcast via shfl
    int mys = 0, mye = 0;
    if (lane < nrows) {
        const int zz = z0 + lane / ny;
        const int yy = y0 + lane % ny;
        const int rowbase = b * NCELLS + (zz * NC1 + yy) * NC1;
        mys:;
        mys = g_off[rowbase + x0];
        mye = g_end[rowbase + x1];
    }

    const unsigned below = (1u << lane) - 1u;
    int cnt = 0;

    for (int r = 0; r < nrows; r++) {
        const int start = __shfl_sync(0xffffffffu, mys, r);
        const int end   = __shfl_sync(0xffffffffu, mye, r);
        for (int k = start; k < end; k += 32) {
            const int kk = k + lane;
            bool valid = false;
            int pi = 0;
            if (kk < end) {
                const float4 p = g_g4[b * NN + kk];
                const float dx = __fsub_rn(cx, p.x);
                const float dy = __fsub_rn(cy, p.y);
                const float dz = __fsub_rn(cz, p.z);
                const float d2 = __fadd_rn(
                    __fadd_rn(__fmul_rn(dx, dx), __fmul_rn(dy, dy)),
                    __fmul_rn(dz, dz));
                valid = d2 < r2;
                pi = __float_as_int(p.w);
            }
            const unsigned m = __ballot_sync(0xffffffffu, valid);
            if (valid) {
                const int pos = cnt + __popc(m & below);
                if (pos < BUFSZ) buf[pos] = (unsigned short)pi;
            }
            cnt += __popc(m);
        }
    }
    if (cnt > BUFSZ) cnt = BUFSZ;
    __syncwarp();

    // rank-select smallest NS into sidx[1..NS] (== scan-order semantics)
    int vmin = 0x7fffffff;
    for (int t = lane; t < cnt; t += 32) {
        const int v = buf[t];
        int rank = 0;
        for (int k = 0; k < cnt; k++) rank += (buf[k] < v);
        if (rank < NS) s_sidx[wid][1 + rank] = v;
        if (v < vmin) vmin = v;
    }
    #pragma unroll
    for (int d = 16; d > 0; d >>= 1) {
        const int o = __shfl_xor_sync(0xffffffffu, vmin, d);
        if (o < vmin) vmin = o;
    }
    const int pad = (cnt > 0) ? vmin : 0;
    if (lane < NS && lane >= cnt) s_sidx[wid][1 + lane] = pad;
    if (lane == 0) s_sidx[wid][0] = fps_idx[w];
    __syncwarp();

    // centered xyz into smem
    {
        const int i = s_sidx[wid][lane];
        const float4 p = g_p4[b * NN + i];
        s_cxs[wid][0][lane] = __fsub_rn(p.x, cx);
        s_cxs[wid][1][lane] = __fsub_rn(p.y, cy);
        s_cxs[wid][2][lane] = __fsub_rn(p.z, cz);
        if (lane == 0) {
            const int i32 = s_sidx[wid][32];
            const float4 q = g_p4[b * NN + i32];
            s_cxs[wid][0][32] = __fsub_rn(q.x, cx);
            s_cxs[wid][1][32] = __fsub_rn(q.y, cy);
            s_cxs[wid][2][32] = __fsub_rn(q.z, cz);
        }
    }
    __syncthreads();

    // ---- Phase B ----
    const size_t chstr = (size_t)NPOINT * NSP;
    float* __restrict__ outb0 =
        out + ((size_t)b * TOTCH * NPOINT + j0) * NSP;

    // xyz channels 0..5 (132 contiguous floats per channel)
    #pragma unroll
    for (int k = 0; k < 6; k++) {
        const int k3 = (k < 3) ? k : k - 3;
        float* __restrict__ dst = outb0 + (size_t)k * chstr;
        {
            const int w4 = (tid * 993) >> 15;     // tid / 33
            const int s  = tid - w4 * 33;
            dst[tid] = s_cxs[w4][k3][s];
        }
        if (tid < 4) dst[128 + tid] = s_cxs[3][k3][29 + tid];
    }

    // features: 4 passes x 16 channels
    const int c4 = lane & 3;        // float4 id within pass (4 channels)
    const int ls = lane >> 2;       // 8 s values per staging iter
    #pragma unroll
    for (int p = 0; p < 4; p++) {
        // staging: warp wid fills columns [wid*33, wid*33+33) of each ch row
        const float4* __restrict__ ftb =
            g_ft4 + (size_t)(b * NN) * 16 + p * 4 + c4;
        #pragma unroll
        for (int s0 = 0; s0 < 32; s0 += 8) {
            const int s = s0 + ls;
            const int i = s_sidx[wid][s];
            const float4 v = ftb[(size_t)i * 16];
            float* tw = &s_tile[(c4 * 4) * TROW + wid * 33 + s];
            tw[0 * TROW] = v.x; tw[1 * TROW] = v.y;
            tw[2 * TROW] = v.z; tw[3 * TROW] = v.w;
        }
        if (lane < 4) {   // s = 32
            const int i = s_sidx[wid][32];
            const float4 v = ftb[(size_t)i * 16];   // c4 = lane
            float* tw = &s_tile[(lane * 4) * TROW + wid * 33 + 32];
            tw[0 * TROW] = v.x; tw[1 * TROW] = v.y;
            tw[2 * TROW] = v.z; tw[3 * TROW] = v.w;
        }
        __syncthreads();

        // writes: 16 ch * 33 float4 = 528 float4, vectorized
        for (int e = tid; e < PCH * 33; e += FW * 32) {
            const int ch = (e * 993) >> 15;        // e / 33
            const int q  = e - ch * 33;
            const float4 v = *(const float4*)&s_tile[ch * TROW + q * 4];
            *(float4*)(outb0 + (size_t)(6 + p * PCH + ch) * chstr + q * 4) = v;
        }
        __syncthreads();
    }
}

// ---------------------------------------------------------------------------
extern "C" void kernel_launch(void* const* d_in, const int* in_sizes, int n_in,
                              void* d_out, int out_size) {
    const float* xyz      = (const float*)d_in[0];   // (B, N, 3)
    const float* new_xyz  = (const float*)d_in[1];   // (B, NPOINT, 3)
    const float* features = (const float*)d_in[2];   // (B, C, N)
    const int*   fps_idx  = (const int*)d_in[3];     // (B, NPOINT)
    float* out = (float*)d_out;

    {
        dim3 grid(NN / 32, CC / 32, BB);
        feat_transpose_kernel<<<grid, 256>>>(features);
    }
    grid_build_kernel<<<BB, 1024>>>(xyz);
    {
        const int blocks = (BB * NPOINT) / FW;   // 2048
        bq_gather_kernel<<<blocks, FW * 32>>>(new_xyz, fps_idx, out);
    }
}